// round 9
// baseline (speedup 1.0000x reference)
#include <cuda_runtime.h>
#include <math.h>

#define T_STEPS 8192
#define HDIM    1024
#define G4      4096
#define NB      128
#define NT      512

typedef unsigned long long u64;

// ── device-global scratch (no runtime allocation) ───────────────────────────
__device__ float g_xg[(size_t)T_STEPS * G4];   // 128 MiB gate preactivations
__device__ float g_y0[(size_t)T_STEPS * HDIM]; // 32 MiB layer-1 outputs
__device__ u64   g_hp[2][HDIM];                // ping-pong {tag:u32 hi, h:f32 lo}

// ── primitives ──────────────────────────────────────────────────────────────
__device__ __forceinline__ void st_strong64(u64* p, u64 v) {
    asm volatile("st.relaxed.gpu.global.b64 [%0], %1;" :: "l"(p), "l"(v) : "memory");
}
// packed dual FMA: d = a*b + d on two fp32 lanes (SASS FFMA2)
__device__ __forceinline__ void ffma2(u64& d, u64 a, u64 b) {
    asm volatile("fma.rn.f32x2 %0, %1, %2, %0;" : "+l"(d) : "l"(a), "l"(b));
}
__device__ __forceinline__ float red2(u64 a, u64 b) {
    float ax, ay, bx, by;
    asm("mov.b64 {%0,%1}, %2;" : "=f"(ax), "=f"(ay) : "l"(a));
    asm("mov.b64 {%0,%1}, %2;" : "=f"(bx), "=f"(by) : "l"(b));
    return (ax + ay) + (bx + by);
}
__device__ __forceinline__ float sig_fast(float x)  { return __fdividef(1.f, 1.f + __expf(-x)); }
__device__ __forceinline__ float tanh_fast(float x) { return __fdividef(2.f, 1.f + __expf(-2.f * x)) - 1.f; }

// ── projection kernel: xg[t][row] = W·src[t] + bi + bh, 4-t tiled ───────────
__global__ void __launch_bounds__(NT, 1)
proj_kernel(const float* __restrict__ src,
            const float* __restrict__ W,
            const float* __restrict__ bi,
            const float* __restrict__ bh)
{
    __shared__ float  shx[4][HDIM];
    __shared__ float4 partV[2][16][32];

    const int tid  = threadIdx.x;
    const int w    = tid >> 5;
    const int lane = tid & 31;
    const int b    = blockIdx.x;
    const int row  = ((lane >> 3) << 10) + (b << 3) + (lane & 7);
    const int kb   = w << 6;

    u64 w2[32];
    {
        const ulonglong2* Wp = reinterpret_cast<const ulonglong2*>(W + (size_t)row * HDIM + kb);
#pragma unroll
        for (int j = 0; j < 16; j++) { ulonglong2 v = Wp[j]; w2[2*j] = v.x; w2[2*j+1] = v.y; }
    }
    float bias = (w == 0) ? (bi[row] + bh[row]) : 0.f;

    float pf[8];
#pragma unroll
    for (int i = 0; i < 4; i++) {
        pf[2*i]   = src[(size_t)i * HDIM + kb + lane];
        pf[2*i+1] = src[(size_t)i * HDIM + kb + 32 + lane];
    }

    for (int tt = 0; tt < T_STEPS; tt += 4) {
#pragma unroll
        for (int i = 0; i < 4; i++) {
            shx[i][kb + lane]      = pf[2*i];
            shx[i][kb + 32 + lane] = pf[2*i+1];
        }
        __syncwarp();
        if (tt + 4 < T_STEPS) {               // prefetch next 4 timesteps
            const float* s2 = src + (size_t)(tt + 4) * HDIM;
#pragma unroll
            for (int i = 0; i < 4; i++) {
                pf[2*i]   = s2[(size_t)i * HDIM + kb + lane];
                pf[2*i+1] = s2[(size_t)i * HDIM + kb + 32 + lane];
            }
        }
        u64 acc[8];
#pragma unroll
        for (int i = 0; i < 8; i++) acc[i] = 0;
#pragma unroll
        for (int j = 0; j < 16; j++) {
#pragma unroll
            for (int i = 0; i < 4; i++) {
                ulonglong2 hv = *reinterpret_cast<const ulonglong2*>(&shx[i][kb + 4*j]);
                ffma2(acc[2*i],   w2[2*j],   hv.x);
                ffma2(acc[2*i+1], w2[2*j+1], hv.y);
            }
        }
        const int p = (tt >> 2) & 1;          // parity double-buffer: 1 bar/4t
        partV[p][w][lane] = make_float4(red2(acc[0], acc[1]), red2(acc[2], acc[3]),
                                        red2(acc[4], acc[5]), red2(acc[6], acc[7]));
        __syncthreads();
        if (w == 0) {
            float s0 = bias, s1 = bias, s2 = bias, s3 = bias;
#pragma unroll
            for (int i = 0; i < 16; i++) {
                float4 v = partV[p][i][lane];
                s0 += v.x; s1 += v.y; s2 += v.z; s3 += v.w;
            }
            g_xg[(size_t)tt * G4 + row]       = s0;
            g_xg[(size_t)(tt + 1) * G4 + row] = s1;
            g_xg[(size_t)(tt + 2) * G4 + row] = s2;
            g_xg[(size_t)(tt + 3) * G4 + row] = s3;
        }
    }
}

// ── scan kernel: tagged {epoch,h} pairs, nanosleep-paced 2-deep poll ────────
template <int LAYER>
__global__ void __launch_bounds__(NT, 1)
scan_kernel(const float* __restrict__ Whh, float* __restrict__ out, unsigned base)
{
    __shared__ float shx[HDIM];
    __shared__ float partS[2][16][32];

    const int tid   = threadIdx.x;
    const int w     = tid >> 5;
    const int lane  = tid & 31;
    const int b     = blockIdx.x;
    const int row   = ((lane >> 3) << 10) + (b << 3) + (lane & 7);
    const int kb    = w << 6;
    const int hbase = b << 3;

    u64 w2[32];
    {
        const ulonglong2* Wp = reinterpret_cast<const ulonglong2*>(Whh + (size_t)row * HDIM + kb);
#pragma unroll
        for (int j = 0; j < 16; j++) { ulonglong2 v = Wp[j]; w2[2*j] = v.x; w2[2*j+1] = v.y; }
    }

    // init own h pairs {tag=base, h=0}. No grid barrier needed: consumers for
    // step `base` spin until this write lands (distinct tags vs prior kernels).
    if (w == 0 && lane < 8)
        st_strong64(&g_hp[base & 1][hbase + lane], ((u64)base << 32));

    float c = 0.f;
    float xg_cur = 0.f;
    if (w == 0) xg_cur = __ldcg(&g_xg[row]);

    for (int t = 0; t < T_STEPS; t++) {
        const unsigned s = base + (unsigned)t;

        // paced 2-deep poll: 2 samples in flight, check the older, pace new
        // issues with nanosleep (HW-sleep: no SMSP issue pressure). Sampling
        // period ~100cyc vs ~330 for a dependent chain; traffic bounded ~3x.
        // Tag in the same 8B atom makes any sample self-validating, so a
        // stale in-flight sample can only delay, never corrupt.
        const ulonglong2* hp = reinterpret_cast<const ulonglong2*>(&g_hp[s & 1][kb]) + lane;
        ulonglong2 v  = __ldcv(hp);
        ulonglong2 vn = __ldcv(hp);
#pragma unroll 1
        for (;;) {
            bool ok = ((unsigned)(v.x >> 32) == s) & ((unsigned)(v.y >> 32) == s);
            if (__all_sync(0xffffffffu, ok)) break;
            __nanosleep(40);
            v = vn;
            vn = __ldcv(hp);
        }
        // stage: one STS.64 per lane
        *reinterpret_cast<float2*>(&shx[kb + 2 * lane]) =
            make_float2(__uint_as_float((unsigned)v.x), __uint_as_float((unsigned)v.y));
        __syncwarp();

        u64 a0 = 0, a1 = 0, a2 = 0, a3 = 0;
#pragma unroll
        for (int j = 0; j < 16; j++) {
            ulonglong2 hv = *reinterpret_cast<const ulonglong2*>(&shx[kb + 4*j]);
            if (j & 1) { ffma2(a2, w2[2*j], hv.x); ffma2(a3, w2[2*j+1], hv.y); }
            else       { ffma2(a0, w2[2*j], hv.x); ffma2(a1, w2[2*j+1], hv.y); }
        }
        const int p = t & 1;                  // parity double-buffer: 1 bar/step
        float partial = red2(a0, a1) + red2(a2, a3);
        if (w == 0) partial += xg_cur;        // fold xg into own partial pre-store
        partS[p][w][lane] = partial;
        __syncthreads();

        if (w == 0) {
            float xnext = (t + 1 < T_STEPS) ? __ldcg(&g_xg[(size_t)(t + 1) * G4 + row]) : 0.f;
            // grouped reduce (low live-register pressure)
            float sg = 0.f;
#pragma unroll
            for (int i = 0; i < 16; i += 4)
                sg += (partS[p][i][lane] + partS[p][i+1][lane]) +
                      (partS[p][i+2][lane] + partS[p][i+3][lane]);

            // torch gate order: i, f, g, o  (lane>>3 selects gate group)
            float act = ((lane >> 3) == 2) ? tanh_fast(sg) : sig_fast(sg);
            const int jj = lane & 7;
            float gi = __shfl_sync(0xffffffffu, act, jj);
            float gf = __shfl_sync(0xffffffffu, act, 8 + jj);
            float gg = __shfl_sync(0xffffffffu, act, 16 + jj);
            float go = __shfl_sync(0xffffffffu, act, 24 + jj);
            if (lane < 8) {
                c = fmaf(gf, c, gi * gg);
                float hn = go * tanh_fast(c);
                // publish first: single predicated STG.64 — tag + value one atom
                u64 pk = ((u64)(s + 1) << 32) | (u64)__float_as_uint(hn);
                st_strong64(&g_hp[(s + 1) & 1][hbase + lane], pk);
                if (LAYER == 0) {
                    g_y0[(size_t)t * HDIM + hbase + lane] = hn;
                } else if (t == T_STEPS - 1) {
                    out[hbase + lane] = hn;
                }
            }
            xg_cur = xnext;
        }
    }
}

extern "C" void kernel_launch(void* const* d_in, const int* in_sizes, int n_in,
                              void* d_out, int out_size)
{
    const float* x    = (const float*)d_in[0];
    const float* Wih0 = (const float*)d_in[1];
    const float* Whh0 = (const float*)d_in[2];
    const float* bi0  = (const float*)d_in[3];
    const float* bh0  = (const float*)d_in[4];
    const float* Wih1 = (const float*)d_in[5];
    const float* Whh1 = (const float*)d_in[6];
    const float* bi1  = (const float*)d_in[7];
    const float* bh1  = (const float*)d_in[8];
    float* out = (float*)d_out;

    // reset h tags each launch (graph-ordered): scan0 step-0 polls pass
    // against {tag=0, h=0}; also clears cross-replay stale tags.
    void* hptr = nullptr; cudaGetSymbolAddress(&hptr, g_hp);
    cudaMemsetAsync(hptr, 0, 2 * HDIM * sizeof(u64));

    // sequential launches = free grid-wide sync between phases.
    proj_kernel<<<NB, NT>>>(x, Wih0, bi0, bh0);
    scan_kernel<0><<<NB, NT>>>(Whh0, nullptr, 0u);
    // scan1 base=16384: tags 16384.. never collide with scan0 leftovers (<=8192)
    float* y0ptr = nullptr; cudaGetSymbolAddress((void**)&y0ptr, g_y0);
    proj_kernel<<<NB, NT>>>(y0ptr, Wih1, bi1, bh1);
    scan_kernel<1><<<NB, NT>>>(Whh1, out, 2u * T_STEPS);
}

// round 10
// speedup vs baseline: 1.2153x; 1.2153x over previous
#include <cuda_runtime.h>
#include <math.h>

#define T_STEPS 8192
#define HDIM    1024
#define G4      4096
#define NB      128
#define NT      512

typedef unsigned long long u64;

// ── device-global scratch (no runtime allocation) ───────────────────────────
__device__ float g_xg[(size_t)T_STEPS * G4];   // 128 MiB gate preactivations
__device__ float g_y0[(size_t)T_STEPS * HDIM]; // 32 MiB layer-1 outputs
__device__ u64   g_hp[2][HDIM];                // ping-pong {tag:u32 hi, h:f32 lo}

// ── primitives ──────────────────────────────────────────────────────────────
__device__ __forceinline__ void st_strong64(u64* p, u64 v) {
    asm volatile("st.relaxed.gpu.global.b64 [%0], %1;" :: "l"(p), "l"(v) : "memory");
}
// packed dual FMA: d = a*b + d on two fp32 lanes (SASS FFMA2)
__device__ __forceinline__ void ffma2(u64& d, u64 a, u64 b) {
    asm volatile("fma.rn.f32x2 %0, %1, %2, %0;" : "+l"(d) : "l"(a), "l"(b));
}
__device__ __forceinline__ float red2(u64 a, u64 b) {
    float ax, ay, bx, by;
    asm("mov.b64 {%0,%1}, %2;" : "=f"(ax), "=f"(ay) : "l"(a));
    asm("mov.b64 {%0,%1}, %2;" : "=f"(bx), "=f"(by) : "l"(b));
    return (ax + ay) + (bx + by);
}
// single-MUFU tanh (sm_75+): ~16cyc vs EX2/ADD/RCP chains
__device__ __forceinline__ float tanh_mufu(float x) {
    float y; asm("tanh.approx.f32 %0, %1;" : "=f"(y) : "f"(x)); return y;
}
__device__ __forceinline__ float sig_mufu(float x) {  // exact identity, 1 MUFU + 1 FMA
    return fmaf(0.5f, tanh_mufu(0.5f * x), 0.5f);
}

// ── projection kernel: xg[t][row] = W·src[t] + bi + bh, 4-t tiled ───────────
__global__ void __launch_bounds__(NT, 1)
proj_kernel(const float* __restrict__ src,
            const float* __restrict__ W,
            const float* __restrict__ bi,
            const float* __restrict__ bh)
{
    __shared__ float  shx[4][HDIM];
    __shared__ float4 partV[2][16][32];

    const int tid  = threadIdx.x;
    const int w    = tid >> 5;
    const int lane = tid & 31;
    const int b    = blockIdx.x;
    const int row  = ((lane >> 3) << 10) + (b << 3) + (lane & 7);
    const int kb   = w << 6;

    u64 w2[32];
    {
        const ulonglong2* Wp = reinterpret_cast<const ulonglong2*>(W + (size_t)row * HDIM + kb);
#pragma unroll
        for (int j = 0; j < 16; j++) { ulonglong2 v = Wp[j]; w2[2*j] = v.x; w2[2*j+1] = v.y; }
    }
    float bias = (w == 0) ? (bi[row] + bh[row]) : 0.f;

    float pf[8];
#pragma unroll
    for (int i = 0; i < 4; i++) {
        pf[2*i]   = src[(size_t)i * HDIM + kb + lane];
        pf[2*i+1] = src[(size_t)i * HDIM + kb + 32 + lane];
    }

    for (int tt = 0; tt < T_STEPS; tt += 4) {
#pragma unroll
        for (int i = 0; i < 4; i++) {
            shx[i][kb + lane]      = pf[2*i];
            shx[i][kb + 32 + lane] = pf[2*i+1];
        }
        __syncwarp();
        if (tt + 4 < T_STEPS) {               // prefetch next 4 timesteps
            const float* s2 = src + (size_t)(tt + 4) * HDIM;
#pragma unroll
            for (int i = 0; i < 4; i++) {
                pf[2*i]   = s2[(size_t)i * HDIM + kb + lane];
                pf[2*i+1] = s2[(size_t)i * HDIM + kb + 32 + lane];
            }
        }
        u64 acc[8];
#pragma unroll
        for (int i = 0; i < 8; i++) acc[i] = 0;
#pragma unroll
        for (int j = 0; j < 16; j++) {
#pragma unroll
            for (int i = 0; i < 4; i++) {
                ulonglong2 hv = *reinterpret_cast<const ulonglong2*>(&shx[i][kb + 4*j]);
                ffma2(acc[2*i],   w2[2*j],   hv.x);
                ffma2(acc[2*i+1], w2[2*j+1], hv.y);
            }
        }
        const int p = (tt >> 2) & 1;          // parity double-buffer: 1 bar/4t
        partV[p][w][lane] = make_float4(red2(acc[0], acc[1]), red2(acc[2], acc[3]),
                                        red2(acc[4], acc[5]), red2(acc[6], acc[7]));
        __syncthreads();
        if (w == 0) {
            float s0 = bias, s1 = bias, s2 = bias, s3 = bias;
#pragma unroll
            for (int i = 0; i < 16; i++) {
                float4 v = partV[p][i][lane];
                s0 += v.x; s1 += v.y; s2 += v.z; s3 += v.w;
            }
            g_xg[(size_t)tt * G4 + row]       = s0;
            g_xg[(size_t)(tt + 1) * G4 + row] = s1;
            g_xg[(size_t)(tt + 2) * G4 + row] = s2;
            g_xg[(size_t)(tt + 3) * G4 + row] = s3;
        }
    }
}

// ── scan kernel: tagged {epoch,h} pairs, phase-offset dual poll chains ──────
template <int LAYER>
__global__ void __launch_bounds__(NT, 1)
scan_kernel(const float* __restrict__ Whh, float* __restrict__ out, unsigned base)
{
    __shared__ float shx[HDIM];
    __shared__ float partS[2][16][32];

    const int tid   = threadIdx.x;
    const int w     = tid >> 5;
    const int lane  = tid & 31;
    const int b     = blockIdx.x;
    const int row   = ((lane >> 3) << 10) + (b << 3) + (lane & 7);
    const int kb    = w << 6;
    const int hbase = b << 3;

    u64 w2[32];
    {
        const ulonglong2* Wp = reinterpret_cast<const ulonglong2*>(Whh + (size_t)row * HDIM + kb);
#pragma unroll
        for (int j = 0; j < 16; j++) { ulonglong2 v = Wp[j]; w2[2*j] = v.x; w2[2*j+1] = v.y; }
    }

    // init own h pairs {tag=base, h=0}. No grid barrier needed: consumers for
    // step `base` spin until this write lands (distinct tags vs prior kernels).
    if (w == 0 && lane < 8)
        st_strong64(&g_hp[base & 1][hbase + lane], ((u64)base << 32));

    float c = 0.f;
    float xg_cur = 0.f;
    if (w == 0) xg_cur = __ldcg(&g_xg[row]);

    for (int t = 0; t < T_STEPS; t++) {
        const unsigned s = base + (unsigned)t;

        // phase-offset dual dependent chains: each chain self-paced at L2 RT
        // (R5-safe); initial ~160cyc dependent-ALU offset between chains makes
        // samples alternate at ~half-period, and the offset self-maintains
        // because each chain reissues only after its own return. Tag in the
        // same 8B atom = every sample self-validating.
        const ulonglong2* hp = reinterpret_cast<const ulonglong2*>(&g_hp[s & 1][kb]) + lane;
        ulonglong2 vA = __ldcv(hp);
        {   // dependent FMUL delay ~160cyc (only on first issue of chain B)
            float d = __uint_as_float(lane + 1);
#pragma unroll
            for (int i = 0; i < 40; i++)
                asm volatile("mul.f32 %0, %0, 0f3F800001;" : "+f"(d));
            if (__float_as_uint(d) == 0xDEADBEEFu) shx[0] = d;  // keep chain live
        }
        ulonglong2 vB = __ldcv(hp);
        ulonglong2 v;
#pragma unroll 1
        for (;;) {
            bool okA = ((unsigned)(vA.x >> 32) == s) & ((unsigned)(vA.y >> 32) == s);
            if (__all_sync(0xffffffffu, okA)) { v = vA; break; }
            vA = __ldcv(hp);
            bool okB = ((unsigned)(vB.x >> 32) == s) & ((unsigned)(vB.y >> 32) == s);
            if (__all_sync(0xffffffffu, okB)) { v = vB; break; }
            vB = __ldcv(hp);
        }
        // stage: one STS.64 per lane
        *reinterpret_cast<float2*>(&shx[kb + 2 * lane]) =
            make_float2(__uint_as_float((unsigned)v.x), __uint_as_float((unsigned)v.y));
        __syncwarp();

        u64 a0 = 0, a1 = 0, a2 = 0, a3 = 0;
#pragma unroll
        for (int j = 0; j < 16; j++) {
            ulonglong2 hv = *reinterpret_cast<const ulonglong2*>(&shx[kb + 4*j]);
            if (j & 1) { ffma2(a2, w2[2*j], hv.x); ffma2(a3, w2[2*j+1], hv.y); }
            else       { ffma2(a0, w2[2*j], hv.x); ffma2(a1, w2[2*j+1], hv.y); }
        }
        const int p = t & 1;                  // parity double-buffer: 1 bar/step
        float partial = red2(a0, a1) + red2(a2, a3);
        if (w == 0) partial += xg_cur;        // fold xg into own partial pre-store
        partS[p][w][lane] = partial;
        __syncthreads();

        if (w == 0) {
            float xnext = (t + 1 < T_STEPS) ? __ldcg(&g_xg[(size_t)(t + 1) * G4 + row]) : 0.f;
            // grouped reduce (low live-register pressure)
            float sg = 0.f;
#pragma unroll
            for (int i = 0; i < 16; i += 4)
                sg += (partS[p][i][lane] + partS[p][i+1][lane]) +
                      (partS[p][i+2][lane] + partS[p][i+3][lane]);

            // torch gate order: i, f, g, o  (lane>>3 selects gate group)
            // single-MUFU activations: tanh direct; sigmoid via identity
            float act = ((lane >> 3) == 2) ? tanh_mufu(sg) : sig_mufu(sg);
            const int jj = lane & 7;
            float gi = __shfl_sync(0xffffffffu, act, jj);
            float gf = __shfl_sync(0xffffffffu, act, 8 + jj);
            float gg = __shfl_sync(0xffffffffu, act, 16 + jj);
            float go = __shfl_sync(0xffffffffu, act, 24 + jj);
            if (lane < 8) {
                c = fmaf(gf, c, gi * gg);
                float hn = go * tanh_mufu(c);
                // publish first: single predicated STG.64 — tag + value one atom
                u64 pk = ((u64)(s + 1) << 32) | (u64)__float_as_uint(hn);
                st_strong64(&g_hp[(s + 1) & 1][hbase + lane], pk);
                if (LAYER == 0) {
                    g_y0[(size_t)t * HDIM + hbase + lane] = hn;
                } else if (t == T_STEPS - 1) {
                    out[hbase + lane] = hn;
                }
            }
            xg_cur = xnext;
        }
    }
}

extern "C" void kernel_launch(void* const* d_in, const int* in_sizes, int n_in,
                              void* d_out, int out_size)
{
    const float* x    = (const float*)d_in[0];
    const float* Wih0 = (const float*)d_in[1];
    const float* Whh0 = (const float*)d_in[2];
    const float* bi0  = (const float*)d_in[3];
    const float* bh0  = (const float*)d_in[4];
    const float* Wih1 = (const float*)d_in[5];
    const float* Whh1 = (const float*)d_in[6];
    const float* bi1  = (const float*)d_in[7];
    const float* bh1  = (const float*)d_in[8];
    float* out = (float*)d_out;

    // reset h tags each launch (graph-ordered): scan0 step-0 polls pass
    // against {tag=0, h=0}; also clears cross-replay stale tags.
    void* hptr = nullptr; cudaGetSymbolAddress(&hptr, g_hp);
    cudaMemsetAsync(hptr, 0, 2 * HDIM * sizeof(u64));

    // sequential launches = free grid-wide sync between phases.
    proj_kernel<<<NB, NT>>>(x, Wih0, bi0, bh0);
    scan_kernel<0><<<NB, NT>>>(Whh0, nullptr, 0u);
    // scan1 base=16384: tags 16384.. never collide with scan0 leftovers (<=8192)
    float* y0ptr = nullptr; cudaGetSymbolAddress((void**)&y0ptr, g_y0);
    proj_kernel<<<NB, NT>>>(y0ptr, Wih1, bi1, bh1);
    scan_kernel<1><<<NB, NT>>>(Whh1, out, 2u * T_STEPS);
}